// round 4
// baseline (speedup 1.0000x reference)
#include <cuda_runtime.h>
#include <cstdint>
#include <cstddef>

// GCN 2-layer: x[N,256] @ W1 -> scatter-agg -> +b1,relu -> @ W2 -> scatter-agg -> +b2
// N = 100000, E = 1.6M, channels 256 -> 128 -> 64.

#define IN_CH  256
#define HIDDEN 128
#define OUT_CH 64
#define NMAX   100000

// scratch (static device arrays; no runtime allocation)
__device__ __align__(16) float g_dinv[NMAX];
__device__ __align__(16) float g_h1[(size_t)NMAX * HIDDEN];
__device__ __align__(16) float g_agg1[(size_t)NMAX * HIDDEN];
__device__ __align__(16) float g_h2[(size_t)NMAX * OUT_CH];
__device__ int g_idx64;   // 1 if edge_index is int64, 0 if int32

// ---------------------------------------------------------------------------
// edge-index dtype detection (device-side, deterministic)
// int64 indices < 2^31 always have zero high words; int32 data reinterpreted
// as int64 packs a second random index into the high word, which is ~never
// all-zero across 16 consecutive entries.
// ---------------------------------------------------------------------------
__global__ void k_detect_idx(const unsigned long long* __restrict__ ei, int E) {
    if (threadIdx.x == 0) {
        int n = E < 16 ? E : 16;
        int is64 = 1;
        for (int i = 0; i < n; i++)
            if ((ei[i] >> 32) != 0ull) is64 = 0;
        g_idx64 = is64;
    }
}

__device__ __forceinline__ int load_idx(const void* ei, long long pos) {
    if (g_idx64) return (int)((const long long*)ei)[pos];
    return ((const int*)ei)[pos];
}

// ---------------------------------------------------------------------------
// small utility kernels
// ---------------------------------------------------------------------------
__global__ void k_set_dinv(float v, int n) {
    int i = blockIdx.x * blockDim.x + threadIdx.x;
    if (i < n) g_dinv[i] = v;
}

__global__ void k_deg(const void* __restrict__ ei, int E) {
    int i = blockIdx.x * blockDim.x + threadIdx.x;
    if (i < E) {
        int d = load_idx(ei, (long long)E + i);   // dst row
        atomicAdd(&g_dinv[d], 1.0f);
    }
}

__global__ void k_rsqrt_dinv(int n) {
    int i = blockIdx.x * blockDim.x + threadIdx.x;
    if (i < n) g_dinv[i] = rsqrtf(g_dinv[i]);
}

// agg1 = relu(agg1 + b1), in place. One thread per float4.
__global__ void k_bias_relu(const float* __restrict__ b, int total4) {
    int i = blockIdx.x * blockDim.x + threadIdx.x;
    if (i >= total4) return;
    int c = (i % (HIDDEN / 4)) * 4;
    float4 v = *(float4*)(g_agg1 + (size_t)i * 4);
    v.x = fmaxf(v.x + b[c + 0], 0.0f);
    v.y = fmaxf(v.y + b[c + 1], 0.0f);
    v.z = fmaxf(v.z + b[c + 2], 0.0f);
    v.w = fmaxf(v.w + b[c + 3], 0.0f);
    *(float4*)(g_agg1 + (size_t)i * 4) = v;
}

// ---------------------------------------------------------------------------
// SGEMM: C[M,N] = A[M,K] @ B[K,N]; epilogue also writes
//   C2[r,c] = (LAYER==2 ? bias[c] : 0) + dinv[r]^2 * acc   (self-loop init)
// LAYER==1: A = Aext (x), C = g_h1, C2 = g_agg1
// LAYER==2: A = g_agg1,   C = g_h2, C2 = C2ext (d_out)
// ---------------------------------------------------------------------------
template<int BM, int BN, int BK, int TM, int TN, int LAYER>
__global__ void sgemm(const float* __restrict__ Aext, const float* __restrict__ B,
                      float* __restrict__ C2ext, const float* __restrict__ bias,
                      int M, int K, int N)
{
    const float* A  = (LAYER == 1) ? Aext   : (const float*)g_agg1;
    float*       C  = (LAYER == 1) ? g_h1   : g_h2;
    float*       C2 = (LAYER == 1) ? g_agg1 : C2ext;

    constexpr int THREADS = (BM / TM) * (BN / TN);
    __shared__ float As[BK][BM + 4];   // transposed A tile, padded
    __shared__ float Bs[BK][BN];

    const int tid = threadIdx.x;
    const int tx = tid % (BN / TN);
    const int ty = tid / (BN / TN);
    const int row0 = blockIdx.x * BM;

    float acc[TM][TN];
#pragma unroll
    for (int i = 0; i < TM; i++)
#pragma unroll
        for (int j = 0; j < TN; j++) acc[i][j] = 0.0f;

    for (int k0 = 0; k0 < K; k0 += BK) {
#pragma unroll
        for (int i = tid * 4; i < BM * BK; i += THREADS * 4) {
            int r = i / BK, c = i % BK;
            int gr = row0 + r;
            float4 v = make_float4(0.f, 0.f, 0.f, 0.f);
            if (gr < M) v = *(const float4*)(A + (size_t)gr * K + k0 + c);
            As[c + 0][r] = v.x;
            As[c + 1][r] = v.y;
            As[c + 2][r] = v.z;
            As[c + 3][r] = v.w;
        }
#pragma unroll
        for (int i = tid * 4; i < BK * BN; i += THREADS * 4) {
            int r = i / BN, c = i % BN;
            *(float4*)&Bs[r][c] = *(const float4*)(B + (size_t)(k0 + r) * N + c);
        }
        __syncthreads();

#pragma unroll
        for (int kk = 0; kk < BK; kk++) {
            float a[TM], b[TN];
#pragma unroll
            for (int i = 0; i < TM; i += 4)
                *(float4*)&a[i] = *(float4*)&As[kk][ty * TM + i];
#pragma unroll
            for (int j = 0; j < TN; j += 4)
                *(float4*)&b[j] = *(float4*)&Bs[kk][tx * TN + j];
#pragma unroll
            for (int i = 0; i < TM; i++)
#pragma unroll
                for (int j = 0; j < TN; j++)
                    acc[i][j] += a[i] * b[j];
        }
        __syncthreads();
    }

#pragma unroll
    for (int i = 0; i < TM; i++) {
        int gr = row0 + ty * TM + i;
        if (gr >= M) continue;
        float di = g_dinv[gr];
        float d2 = di * di;
#pragma unroll
        for (int j = 0; j < TN; j += 4) {
            int gc = tx * TN + j;
            float4 v = make_float4(acc[i][j], acc[i][j + 1], acc[i][j + 2], acc[i][j + 3]);
            *(float4*)(C + (size_t)gr * N + gc) = v;
            float4 w;
            w.x = d2 * v.x; w.y = d2 * v.y; w.z = d2 * v.z; w.w = d2 * v.w;
            if (LAYER == 2) {
                w.x += bias[gc + 0];
                w.y += bias[gc + 1];
                w.z += bias[gc + 2];
                w.w += bias[gc + 3];
            }
            *(float4*)(C2 + (size_t)gr * N + gc) = w;
        }
    }
}

// ---------------------------------------------------------------------------
// edge scatter: agg[dst] += h[src] * dinv[src]*dinv[dst]
// NF4 = row width in float4s. One thread per (edge, float4).
// ---------------------------------------------------------------------------
template<int NF4, int LAYER>
__global__ void k_scatter(const void* __restrict__ ei,
                          float* __restrict__ aggext, int E)
{
    const float* h   = (LAYER == 1) ? (const float*)g_h1 : (const float*)g_h2;
    float*       agg = (LAYER == 1) ? g_agg1 : aggext;

    long long t = (long long)blockIdx.x * blockDim.x + threadIdx.x;
    int e = (int)(t / NF4);
    int c = (int)(t % NF4);
    if (e >= E) return;
    int s = load_idx(ei, e);
    int d = load_idx(ei, (long long)E + e);
    float nrm = g_dinv[s] * g_dinv[d];
    float4 v = *(const float4*)(h + (size_t)s * (NF4 * 4) + c * 4);
    v.x *= nrm; v.y *= nrm; v.z *= nrm; v.w *= nrm;
    atomicAdd((float4*)(agg + (size_t)d * (NF4 * 4) + c * 4), v);
}

// ---------------------------------------------------------------------------
extern "C" void kernel_launch(void* const* d_in, const int* in_sizes, int n_in,
                              void* d_out, int out_size)
{
    const float* x  = (const float*)d_in[0];
    const void*  ei = d_in[1];                   // int32 or int64, detected on device
    const float* W1 = (const float*)d_in[2];
    const float* b1 = (const float*)d_in[3];
    const float* W2 = (const float*)d_in[4];
    const float* b2 = (const float*)d_in[5];
    float* out = (float*)d_out;

    int N = in_sizes[0] / IN_CH;   // 100000
    int E = in_sizes[1] / 2;       // 1600000

    const int T = 256;

    // detect edge_index dtype
    k_detect_idx<<<1, 32>>>((const unsigned long long*)ei, E);

    // degree (with self-loop) -> dinv
    k_set_dinv<<<(N + T - 1) / T, T>>>(1.0f, N);
    k_deg<<<(E + T - 1) / T, T>>>(ei, E);
    k_rsqrt_dinv<<<(N + T - 1) / T, T>>>(N);

    // layer 1: h1 = x @ W1 ; agg1 = dinv^2 * h1 (self-loop)
    sgemm<128, 128, 8, 8, 8, 1><<<(N + 127) / 128, 256>>>(
        x, W1, nullptr, nullptr, N, IN_CH, HIDDEN);

    // agg1[dst] += h1[src] * norm
    {
        long long tt = (long long)E * (HIDDEN / 4);
        k_scatter<HIDDEN / 4, 1><<<(int)((tt + 255) / 256), 256>>>(ei, nullptr, E);
    }

    // agg1 = relu(agg1 + b1) (in place)
    {
        int tot4 = N * HIDDEN / 4;
        k_bias_relu<<<(tot4 + T - 1) / T, T>>>(b1, tot4);
    }

    // layer 2: h2 = agg1 @ W2 ; out = b2 + dinv^2 * h2
    sgemm<128, 64, 8, 8, 8, 2><<<(N + 127) / 128, 128>>>(
        nullptr, W2, out, b2, N, HIDDEN, OUT_CH);

    // out[dst] += h2[src] * norm
    {
        long long tt = (long long)E * (OUT_CH / 4);
        k_scatter<OUT_CH / 4, 2><<<(int)((tt + 255) / 256), 256>>>(ei, out, E);
    }
}

// round 6
// speedup vs baseline: 1.2765x; 1.2765x over previous
#include <cuda_runtime.h>
#include <cstdint>
#include <cstddef>

// GCN 2-layer: x[N,256] @ W1 -> scatter-agg -> +b1,relu -> @ W2 -> scatter-agg -> +b2
// N = 100000, E = 1.6M, channels 256 -> 128 -> 64.
// GEMMs on tensor cores (tf32 mma.sync, fp32 accumulate).

#define IN_CH  256
#define HIDDEN 128
#define OUT_CH 64
#define NMAX   100000
#define EMAX   1600000

// scratch (static device arrays; no runtime allocation)
__device__ __align__(16) float g_dinv[NMAX];
__device__ __align__(16) float g_h1[(size_t)NMAX * HIDDEN];
__device__ __align__(16) float g_agg1[(size_t)NMAX * HIDDEN];
__device__ __align__(16) float g_h2[(size_t)NMAX * OUT_CH];
__device__ __align__(16) int   g_esrc[EMAX];
__device__ __align__(16) int   g_edst[EMAX];
__device__ __align__(16) float g_enorm[EMAX];
__device__ int g_idx64;   // 1 if edge_index is int64, 0 if int32

// ---------------------------------------------------------------------------
// edge-index dtype detection (device-side, deterministic)
// ---------------------------------------------------------------------------
__global__ void k_detect_idx(const unsigned long long* __restrict__ ei, int E) {
    if (threadIdx.x == 0) {
        int n = E < 16 ? E : 16;
        int is64 = 1;
        for (int i = 0; i < n; i++)
            if ((ei[i] >> 32) != 0ull) is64 = 0;
        g_idx64 = is64;
    }
}

__device__ __forceinline__ int load_idx(const void* ei, long long pos) {
    if (g_idx64) return (int)((const long long*)ei)[pos];
    return ((const int*)ei)[pos];
}

// ---------------------------------------------------------------------------
// small utility kernels
// ---------------------------------------------------------------------------
__global__ void k_set_dinv(float v, int n) {
    int i = blockIdx.x * blockDim.x + threadIdx.x;
    if (i < n) g_dinv[i] = v;
}

__global__ void k_deg(const void* __restrict__ ei, int E) {
    int i = blockIdx.x * blockDim.x + threadIdx.x;
    if (i < E) {
        int d = load_idx(ei, (long long)E + i);
        atomicAdd(&g_dinv[d], 1.0f);
    }
}

__global__ void k_rsqrt_dinv(int n) {
    int i = blockIdx.x * blockDim.x + threadIdx.x;
    if (i < n) g_dinv[i] = rsqrtf(g_dinv[i]);
}

// pack (src, dst, norm) once; scatters then avoid dtype branch + dinv gathers
__global__ void k_prep_edges(const void* __restrict__ ei, int E) {
    int i = blockIdx.x * blockDim.x + threadIdx.x;
    if (i >= E) return;
    int s = load_idx(ei, i);
    int d = load_idx(ei, (long long)E + i);
    g_esrc[i] = s;
    g_edst[i] = d;
    g_enorm[i] = g_dinv[s] * g_dinv[d];
}

// agg1 = relu(agg1 + b1), in place. One thread per float4.
__global__ void k_bias_relu(const float* __restrict__ b, int total4) {
    int i = blockIdx.x * blockDim.x + threadIdx.x;
    if (i >= total4) return;
    int c = (i % (HIDDEN / 4)) * 4;
    float4 v = *(float4*)(g_agg1 + (size_t)i * 4);
    v.x = fmaxf(v.x + b[c + 0], 0.0f);
    v.y = fmaxf(v.y + b[c + 1], 0.0f);
    v.z = fmaxf(v.z + b[c + 2], 0.0f);
    v.w = fmaxf(v.w + b[c + 3], 0.0f);
    *(float4*)(g_agg1 + (size_t)i * 4) = v;
}

// ---------------------------------------------------------------------------
// tf32 tensor-core GEMM: C[M,N] = A[M,K] @ B[K,N]; fused epilogue also writes
//   C2[r,c] = (LAYER==2 ? bias[c] : 0) + dinv[r]^2 * acc   (self-loop init)
// LAYER==1: A = Aext (x), C = g_h1, C2 = g_agg1
// LAYER==2: A = g_agg1,   C = g_h2, C2 = C2ext (d_out)
// ---------------------------------------------------------------------------
__device__ __forceinline__ uint32_t f2tf32(float x) {
    uint32_t r;
    asm("cvt.rna.tf32.f32 %0, %1;" : "=r"(r) : "f"(x));
    return r;
}

__device__ __forceinline__ void mma_tf32(float* c, const uint32_t* a, const uint32_t* b) {
    asm volatile(
        "mma.sync.aligned.m16n8k8.row.col.f32.tf32.tf32.f32 "
        "{%0,%1,%2,%3}, {%4,%5,%6,%7}, {%8,%9}, {%0,%1,%2,%3};"
        : "+f"(c[0]), "+f"(c[1]), "+f"(c[2]), "+f"(c[3])
        : "r"(a[0]), "r"(a[1]), "r"(a[2]), "r"(a[3]), "r"(b[0]), "r"(b[1]));
}

template<int BM, int BN, int BK, int LAYER>
__global__ void gemm_tf32(const float* __restrict__ Aext, const float* __restrict__ B,
                          float* __restrict__ C2ext, const float* __restrict__ bias,
                          int M, int K, int N)
{
    const float* A  = (LAYER == 1) ? Aext   : (const float*)g_agg1;
    float*       C  = (LAYER == 1) ? g_h1   : g_h2;
    float*       C2 = (LAYER == 1) ? g_agg1 : C2ext;

    constexpr int WARPS_M = 4, WARPS_N = 2;
    constexpr int THREADS = WARPS_M * WARPS_N * 32;   // 256
    constexpr int WM = BM / WARPS_M;                  // 32
    constexpr int WN = BN / WARPS_N;                  // 64 (L1) / 32 (L2)
    constexpr int MT = WM / 16;                       // 2
    constexpr int NT = WN / 8;                        // 8 / 4
    constexpr int APAD = 4, BPAD = 8;                 // conflict-free fragment LDS

    __shared__ uint32_t As[BM][BK + APAD];
    __shared__ uint32_t Bs[BK][BN + BPAD];

    const int tid  = threadIdx.x;
    const int wid  = tid >> 5;
    const int lane = tid & 31;
    const int gq   = lane >> 2;   // groupID
    const int tg   = lane & 3;    // thread-in-group
    const int wm   = wid % WARPS_M;
    const int wn   = wid / WARPS_M;
    const int row0 = blockIdx.x * BM;

    float acc[MT][NT][4];
#pragma unroll
    for (int i = 0; i < MT; i++)
#pragma unroll
        for (int j = 0; j < NT; j++)
#pragma unroll
            for (int q = 0; q < 4; q++) acc[i][j][q] = 0.0f;

    for (int k0 = 0; k0 < K; k0 += BK) {
        // A tile: BM x BK (row-major), converted to tf32 bits
#pragma unroll
        for (int i = tid * 4; i < BM * BK; i += THREADS * 4) {
            int r = i / BK, c = i % BK;
            int gr = row0 + r;
            float4 v = make_float4(0.f, 0.f, 0.f, 0.f);
            if (gr < M) v = *(const float4*)(A + (size_t)gr * K + k0 + c);
            As[r][c + 0] = f2tf32(v.x);
            As[r][c + 1] = f2tf32(v.y);
            As[r][c + 2] = f2tf32(v.z);
            As[r][c + 3] = f2tf32(v.w);
        }
        // B tile: BK x BN
#pragma unroll
        for (int i = tid * 4; i < BK * BN; i += THREADS * 4) {
            int r = i / BN, c = i % BN;
            float4 v = *(const float4*)(B + (size_t)(k0 + r) * N + c);
            Bs[r][c + 0] = f2tf32(v.x);
            Bs[r][c + 1] = f2tf32(v.y);
            Bs[r][c + 2] = f2tf32(v.z);
            Bs[r][c + 3] = f2tf32(v.w);
        }
        __syncthreads();

#pragma unroll
        for (int kk = 0; kk < BK; kk += 8) {
            uint32_t af[MT][4];
#pragma unroll
            for (int mt = 0; mt < MT; mt++) {
                int r = wm * WM + mt * 16 + gq;
                af[mt][0] = As[r][kk + tg];
                af[mt][1] = As[r + 8][kk + tg];
                af[mt][2] = As[r][kk + tg + 4];
                af[mt][3] = As[r + 8][kk + tg + 4];
            }
            uint32_t bf[NT][2];
#pragma unroll
            for (int nt = 0; nt < NT; nt++) {
                int c = wn * WN + nt * 8 + gq;
                bf[nt][0] = Bs[kk + tg][c];
                bf[nt][1] = Bs[kk + tg + 4][c];
            }
#pragma unroll
            for (int mt = 0; mt < MT; mt++)
#pragma unroll
                for (int nt = 0; nt < NT; nt++)
                    mma_tf32(acc[mt][nt], af[mt], bf[nt]);
        }
        __syncthreads();
    }

    // epilogue: c0,c1 -> (row, col..col+1); c2,c3 -> (row+8, ...)
#pragma unroll
    for (int mt = 0; mt < MT; mt++) {
#pragma unroll
        for (int half = 0; half < 2; half++) {
            int row = row0 + wm * WM + mt * 16 + gq + 8 * half;
            if (row >= M) continue;
            float di = g_dinv[row];
            float d2 = di * di;
#pragma unroll
            for (int nt = 0; nt < NT; nt++) {
                int col = wn * WN + nt * 8 + 2 * tg;
                float v0 = acc[mt][nt][2 * half + 0];
                float v1 = acc[mt][nt][2 * half + 1];
                *(float2*)(C + (size_t)row * N + col) = make_float2(v0, v1);
                float w0 = d2 * v0, w1 = d2 * v1;
                if (LAYER == 2) { w0 += bias[col]; w1 += bias[col + 1]; }
                *(float2*)(C2 + (size_t)row * N + col) = make_float2(w0, w1);
            }
        }
    }
}

// ---------------------------------------------------------------------------
// edge scatter: agg[dst] += h[src] * norm   (packed edge list)
// NF4 = row width in float4s. One thread per (edge, float4).
// ---------------------------------------------------------------------------
template<int NF4, int LAYER>
__global__ void k_scatter(float* __restrict__ aggext, int E)
{
    const float* h   = (LAYER == 1) ? (const float*)g_h1 : (const float*)g_h2;
    float*       agg = (LAYER == 1) ? g_agg1 : aggext;

    long long t = (long long)blockIdx.x * blockDim.x + threadIdx.x;
    int e = (int)(t / NF4);
    int c = (int)(t % NF4);
    if (e >= E) return;
    int s = g_esrc[e];
    int d = g_edst[e];
    float nrm = g_enorm[e];
    float4 v = *(const float4*)(h + (size_t)s * (NF4 * 4) + c * 4);
    v.x *= nrm; v.y *= nrm; v.z *= nrm; v.w *= nrm;
    atomicAdd((float4*)(agg + (size_t)d * (NF4 * 4) + c * 4), v);
}

// ---------------------------------------------------------------------------
extern "C" void kernel_launch(void* const* d_in, const int* in_sizes, int n_in,
                              void* d_out, int out_size)
{
    const float* x  = (const float*)d_in[0];
    const void*  ei = d_in[1];                   // int32 or int64, detected on device
    const float* W1 = (const float*)d_in[2];
    const float* b1 = (const float*)d_in[3];
    const float* W2 = (const float*)d_in[4];
    const float* b2 = (const float*)d_in[5];
    float* out = (float*)d_out;

    int N = in_sizes[0] / IN_CH;   // 100000
    int E = in_sizes[1] / 2;       // 1600000

    const int T = 256;

    k_detect_idx<<<1, 32>>>((const unsigned long long*)ei, E);

    // degree (with self-loop) -> dinv -> packed edges
    k_set_dinv<<<(N + T - 1) / T, T>>>(1.0f, N);
    k_deg<<<(E + T - 1) / T, T>>>(ei, E);
    k_rsqrt_dinv<<<(N + T - 1) / T, T>>>(N);
    k_prep_edges<<<(E + T - 1) / T, T>>>(ei, E);

    // layer 1: h1 = x @ W1 ; agg1 = dinv^2 * h1 (self-loop)
    gemm_tf32<128, 128, 32, 1><<<(N + 127) / 128, 256>>>(
        x, W1, nullptr, nullptr, N, IN_CH, HIDDEN);

    // agg1[dst] += h1[src] * norm
    {
        long long tt = (long long)E * (HIDDEN / 4);
        k_scatter<HIDDEN / 4, 1><<<(int)((tt + 255) / 256), 256>>>(nullptr, E);
    }

    // agg1 = relu(agg1 + b1) (in place)
    {
        int tot4 = N * HIDDEN / 4;
        k_bias_relu<<<(tot4 + T - 1) / T, T>>>(b1, tot4);
    }

    // layer 2: h2 = agg1 @ W2 ; out = b2 + dinv^2 * h2
    gemm_tf32<128, 64, 32, 2><<<(N + 127) / 128, 256>>>(
        nullptr, W2, out, b2, N, HIDDEN, OUT_CH);

    // out[dst] += h2[src] * norm
    {
        long long tt = (long long)E * (OUT_CH / 4);
        k_scatter<OUT_CH / 4, 2><<<(int)((tt + 255) / 256), 256>>>(out, E);
    }
}